// round 3
// baseline (speedup 1.0000x reference)
#include <cuda_runtime.h>

// pRNN_45492293599807 — only node N-1 is observed by the outputs.
// Live work per batch row: gather 32 values, one 32x32 matvec + one 32-dot.
//
// Shapes (fixed by the problem):
//   B=1024, I=256, N=2048, D=32, C=32
// Inputs (metadata order):
//   0: x      (B, I)        float32
//   1: h0     (B, N, D)     float32   (zeros in setup, but read for correctness)
//   2: conv_w (I,)          float32
//   3: conv_b (I,)          float32
//   4: W      (N, D, C)     float32
//   5: b      (N, D)        float32
//   6: W_out  (1, C)        float32
//   7: b_out  (1,)          float32
//   8: idx    (N, C)        int32, values in [0, I + N*D)
// Output: [ out_nodes[:, -1] (B, D) | out2 (B, 1) ]  -> B*D + B floats
//
// Design: 1 warp per batch row, 8 warps/block, 128 blocks (single wave).
// No shared memory, no barriers: lane d's W row W[N-1, d, :] is a contiguous
// 128B span loaded as 8x float4 into registers (L2-broadcast across blocks,
// L1 hit for warps 1..7 of each block). All loads are issued up front so the
// single DRAM/L2 latency exposure is paid once, overlapped.

#define PB 1024
#define PI 256
#define PN 2048
#define PD 32
#define PC 32

__global__ __launch_bounds__(256, 8)
void prnn_last_node_kernel(const float* __restrict__ x,
                           const float* __restrict__ h0,
                           const float* __restrict__ conv_w,
                           const float* __restrict__ conv_b,
                           const float* __restrict__ W,
                           const float* __restrict__ bias,
                           const float* __restrict__ W_out,
                           const float* __restrict__ b_out,
                           const int*   __restrict__ idx,
                           float* __restrict__ out)
{
    const int tid  = threadIdx.x;
    const int warp = tid >> 5;
    const int lane = tid & 31;
    const int b    = blockIdx.x * 8 + warp;   // one batch row per warp

    // ---- independent loads, issued up front (MLP ~ 11 per lane) ----

    // idx row N-1: one 128B line, broadcast to every block via L2.
    const int j = idx[(PN - 1) * PC + lane];

    // W row for this lane: W[N-1, lane, 0..31] — contiguous 128 bytes.
    const float4* wrow4 =
        (const float4*)(W + ((size_t)(PN - 1) * PD + lane) * PC);
    float4 w0 = wrow4[0], w1 = wrow4[1], w2 = wrow4[2], w3 = wrow4[3];
    float4 w4 = wrow4[4], w5 = wrow4[5], w6 = wrow4[6], w7 = wrow4[7];

    const float bl  = bias[(PN - 1) * PD + lane];
    const float wo  = W_out[lane];
    const float bo  = b_out[0];

    // ---- gather: g = buf[b, j] (data-dependent load) ----
    float g;
    if (j < PI) {
        float v = fmaf(x[(size_t)b * PI + j], conv_w[j], conv_b[j]);
        g = v > 0.0f ? v : 0.0f;          // relu(conv)
    } else {
        g = h0[(size_t)b * (PN * PD) + (j - PI)];   // h0.reshape(B, N*D)
    }

    // ---- out_nodes[:, -1]: lane == d; broadcast g[c] via shfl ----
    float wreg[PC] = {
        w0.x, w0.y, w0.z, w0.w,  w1.x, w1.y, w1.z, w1.w,
        w2.x, w2.y, w2.z, w2.w,  w3.x, w3.y, w3.z, w3.w,
        w4.x, w4.y, w4.z, w4.w,  w5.x, w5.y, w5.z, w5.w,
        w6.x, w6.y, w6.z, w6.w,  w7.x, w7.y, w7.z, w7.w
    };

    float acc  = bl;
    float acc2 = g * wo;                  // out2 partial (lane == c)
    #pragma unroll
    for (int c = 0; c < PC; c++) {
        float gc = __shfl_sync(0xffffffffu, g, c);
        acc = fmaf(gc, wreg[c], acc);
    }
    acc = acc > 0.0f ? acc : 0.0f;
    out[(size_t)b * PD + lane] = acc;

    // ---- out2[b]: butterfly reduce of g[c] * W_out[c] ----
    #pragma unroll
    for (int o = 16; o > 0; o >>= 1)
        acc2 += __shfl_xor_sync(0xffffffffu, acc2, o);
    if (lane == 0) {
        float v = acc2 + bo;
        out[PB * PD + b] = v > 0.0f ? v : 0.0f;
    }
}

extern "C" void kernel_launch(void* const* d_in, const int* in_sizes, int n_in,
                              void* d_out, int out_size)
{
    const float* x      = (const float*)d_in[0];
    const float* h0     = (const float*)d_in[1];
    const float* conv_w = (const float*)d_in[2];
    const float* conv_b = (const float*)d_in[3];
    const float* W      = (const float*)d_in[4];
    const float* bias   = (const float*)d_in[5];
    const float* W_out  = (const float*)d_in[6];
    const float* b_out  = (const float*)d_in[7];
    const int*   idx    = (const int*)d_in[8];
    float* out = (float*)d_out;

    // 8 batch rows per block (one per warp), 1024/8 = 128 blocks.
    prnn_last_node_kernel<<<PB / 8, 256>>>(x, h0, conv_w, conv_b, W, bias,
                                           W_out, b_out, idx, out);
}